// round 4
// baseline (speedup 1.0000x reference)
#include <cuda_runtime.h>

#define BATCH 4
#define C 64
#define N 8192
#define O 128
#define KNN 20
#define C2 128
#define NB 32
#define FT_STRIDE 24

// kNN tiling
#define QT 64              // queries per block
#define CT 64              // candidates per tile
#define QS4 17             // query/cand tile row stride in float4 (68 floats)
#define DS_STRIDE 65       // distance tile row stride in floats

// Scratch (allocation-free rule: __device__ globals)
__device__ float g_xt[BATCH * N * C];    // (b, n, c) transposed points
__device__ float g_xx[BATCH * N];        // squared norms
__device__ int   g_idx[BATCH * N * KNN]; // knn indices
__device__ float g_W1T[C2 * C2];         // [c][d] = W1[d][c]
__device__ float g_W2T[C2 * C2];         // [c][o] = W2[o][c]

// ---------------------------------------------------------------------------
// Kernel 1: transpose x (b,c,n) -> xt (b,n,c) and compute squared norms
// ---------------------------------------------------------------------------
__global__ __launch_bounds__(256) void prep_kernel(const float* __restrict__ x) {
    int gid = blockIdx.x * 256 + threadIdx.x;     // gid = b*N + n
    int b = gid >> 13;
    int n = gid & (N - 1);
    const float* xb = x + (size_t)b * C * N;
    float v[C];
    float s = 0.f;
#pragma unroll
    for (int c = 0; c < C; c++) {
        v[c] = xb[(size_t)c * N + n];             // coalesced across threads
        s = fmaf(v[c], v[c], s);
    }
    g_xx[gid] = s;
    float4* dst = (float4*)(g_xt + (size_t)gid * C);
#pragma unroll
    for (int i = 0; i < C / 4; i++)
        dst[i] = make_float4(v[4*i], v[4*i+1], v[4*i+2], v[4*i+3]);
}

// ---------------------------------------------------------------------------
// Kernel 1b: transpose W1, W2 into global scratch (tiny)
// ---------------------------------------------------------------------------
__global__ __launch_bounds__(256) void wtrans_kernel(const float* __restrict__ W1,
                                                     const float* __restrict__ W2) {
    int i = blockIdx.x * 256 + threadIdx.x;       // i = d*128 + c
    int d = i >> 7, c = i & 127;
    g_W1T[c * C2 + d] = W1[i];
    g_W2T[c * C2 + d] = W2[i];
}

// ---------------------------------------------------------------------------
// streaming top-KNN insertion (register arrays, fully unrolled predication)
// ---------------------------------------------------------------------------
__device__ __forceinline__ void topk_insert(float d, int m, float* bd, int* bi,
                                            float& worst, int& wpos) {
    if (d < worst) {
#pragma unroll
        for (int i = 0; i < KNN; i++)
            if (i == wpos) { bd[i] = d; bi[i] = m; }
        worst = bd[0]; wpos = 0;
#pragma unroll
        for (int i = 1; i < KNN; i++)
            if (bd[i] > worst) { worst = bd[i]; wpos = i; }
    }
}

// ---------------------------------------------------------------------------
// Kernel 2: brute-force kNN, GEMM-style register-tiled distance computation.
// Block = 128 threads, 64 queries. Per 64-candidate tile:
//   phase A: each thread computes a 4x8 register tile of -dot products
//            (12 LDS.128 -> 128 FFMA per c4 chunk, ratio 10.7:1)
//   phase B: distances in smem; 2 threads per query scan disjoint halves,
//            streaming top-20 in registers (set only; softmax over k is
//            permutation-invariant, so no sorting anywhere).
// 50.5KB smem -> 4 blocks/SM -> 16 warps/SM, single wave (512 blocks).
// ---------------------------------------------------------------------------
__global__ __launch_bounds__(128, 4) void knn_kernel() {
    extern __shared__ float sm[];
    float* qs  = sm;                       // [QT][68] query tile
    float* xs  = qs + QT * 68;             // [CT][68] candidate tile
    float* ds  = xs + CT * 68;             // [QT][DS_STRIDE] distances
    float* xxs = ds + QT * DS_STRIDE;      // [CT]

    int t  = threadIdx.x;
    int tx = t & 7;                        // candidate lane: m = tx + 8*cj
    int ty = t >> 3;                       // query lane: q = ty + 16*qi
    int b  = blockIdx.y;
    size_t bN = (size_t)b * N;
    int q0 = blockIdx.x * QT;

    // Stage query tile (coalesced, conflict-free stride-17 f4 writes)
    {
        const float4* src = (const float4*)(g_xt + (bN + q0) * C);
        float4* dst = (float4*)qs;
#pragma unroll
        for (int i = 0; i < 8; i++) {
            int j = i * 128 + t;
            dst[(j >> 4) * QS4 + (j & 15)] = src[j];
        }
    }

    float bd[KNN];
    int   bi[KNN];
#pragma unroll
    for (int i = 0; i < KNN; i++) { bd[i] = 3.4e38f; bi[i] = 0; }
    float worst = 3.4e38f;
    int   wpos  = 0;

    const float4* qb = (const float4*)qs + ty * QS4;   // query row base
    const float4* xb = (const float4*)xs + tx * QS4;   // candidate row base

    for (int m0 = 0; m0 < N; m0 += CT) {
        __syncthreads();
        // Candidate tile load (coalesced)
        {
            const float4* src = (const float4*)(g_xt + (bN + m0) * C);
            float4* dst = (float4*)xs;
#pragma unroll
            for (int i = 0; i < 8; i++) {
                int j = i * 128 + t;
                dst[(j >> 4) * QS4 + (j & 15)] = src[j];
            }
            if (t < CT) xxs[t] = g_xx[bN + m0 + t];
        }
        __syncthreads();

        // ---- phase A: 4x8 register tile of dot products ----
        float acc[4][8];
#pragma unroll
        for (int qi = 0; qi < 4; qi++)
#pragma unroll
            for (int cj = 0; cj < 8; cj++) acc[qi][cj] = 0.f;

#pragma unroll 4
        for (int i = 0; i < 16; i++) {
            float4 qf0 = qb[ 0 * QS4 + i];
            float4 qf1 = qb[16 * QS4 + i];
            float4 qf2 = qb[32 * QS4 + i];
            float4 qf3 = qb[48 * QS4 + i];
#pragma unroll
            for (int cj = 0; cj < 8; cj++) {
                float4 cf = xb[(8 * cj) * QS4 + i];
                float* a0 = &acc[0][cj];
                float* a1 = &acc[1][cj];
                float* a2 = &acc[2][cj];
                float* a3 = &acc[3][cj];
                *a0 = fmaf(qf0.x, cf.x, *a0); *a0 = fmaf(qf0.y, cf.y, *a0);
                *a0 = fmaf(qf0.z, cf.z, *a0); *a0 = fmaf(qf0.w, cf.w, *a0);
                *a1 = fmaf(qf1.x, cf.x, *a1); *a1 = fmaf(qf1.y, cf.y, *a1);
                *a1 = fmaf(qf1.z, cf.z, *a1); *a1 = fmaf(qf1.w, cf.w, *a1);
                *a2 = fmaf(qf2.x, cf.x, *a2); *a2 = fmaf(qf2.y, cf.y, *a2);
                *a2 = fmaf(qf2.z, cf.z, *a2); *a2 = fmaf(qf2.w, cf.w, *a2);
                *a3 = fmaf(qf3.x, cf.x, *a3); *a3 = fmaf(qf3.y, cf.y, *a3);
                *a3 = fmaf(qf3.z, cf.z, *a3); *a3 = fmaf(qf3.w, cf.w, *a3);
            }
        }

        // epilogue: d = xx_cand - 2*dot  (xx_query is constant per query ->
        // irrelevant for top-k ordering)
#pragma unroll
        for (int cj = 0; cj < 8; cj++) {
            float xc = xxs[tx + 8 * cj];
#pragma unroll
            for (int qi = 0; qi < 4; qi++)
                ds[(ty + 16 * qi) * DS_STRIDE + tx + 8 * cj] =
                    fmaf(-2.f, acc[qi][cj], xc);
        }
        __syncthreads();

        // ---- phase B: streaming top-k scan (2 threads per query) ----
        {
            int ql   = t & 63;
            int half = t >> 6;
            const float* dr = ds + ql * DS_STRIDE + half * 32;
            int mb = m0 + half * 32;
#pragma unroll 4
            for (int j = 0; j < 32; j++)
                topk_insert(dr[j], mb + j, bd, bi, worst, wpos);
        }
    }

    // Merge the two half-lists per query (reuse smem)
    __syncthreads();
    float* md = sm;                          // [128][KNN] dists
    int*   mi = (int*)(sm + 128 * KNN);      // [128][KNN] idxs
#pragma unroll
    for (int i = 0; i < KNN; i++) { md[t * KNN + i] = bd[i]; mi[t * KNN + i] = bi[i]; }
    __syncthreads();
    if (t < 64) {
#pragma unroll
        for (int i = 0; i < KNN; i++)
            topk_insert(md[(t + 64) * KNN + i], mi[(t + 64) * KNN + i],
                        bd, bi, worst, wpos);
        int* op = g_idx + (bN + q0 + t) * KNN;
#pragma unroll
        for (int i = 0; i < KNN; i++) op[i] = bi[i];
    }
}

static const int KNN_SMEM_BYTES = (QT * 68 + CT * 68 + QT * DS_STRIDE + CT) * 4;

// ---------------------------------------------------------------------------
// Kernel 3: gather feats, h = feats@W1^T, softmax over k, g[c]=sum_k f*gate,
// out[o] = sum_c g[c]*W2T[c][o].  (unchanged from round 2)
// ---------------------------------------------------------------------------
__global__ __launch_bounds__(256) void mlp_kernel(float* __restrict__ out) {
    __shared__ float fT[2 * C2 * FT_STRIDE];
    __shared__ float cs[2 * C];
    __shared__ float gs[2 * C2];
    __shared__ int   nbs[2 * 32];
    __shared__ float obuf[O * 33];

    int tid = threadIdx.x;
    int sub = tid >> 7;
    int t   = tid & 127;
    int b   = blockIdx.y;
    int n0  = blockIdx.x * NB;
    int barid = sub + 1;

    float* fTs  = fT  + sub * C2 * FT_STRIDE;
    float* css  = cs  + sub * C;
    float* gss  = gs  + sub * C2;
    int*   nbss = nbs + sub * 32;
    size_t bN = (size_t)b * N;

    for (int it = 0; it < NB / 2; it++) {
        int n = n0 + 2 * it + sub;
        size_t base = bN + n;

        if (t < KNN) nbss[t] = g_idx[base * KNN + t];
        if (t < C)   css[t]  = g_xt[base * C + t];
        asm volatile("bar.sync %0, 128;" :: "r"(barid));

#pragma unroll
        for (int jj = 0; jj < (KNN * C) / 128; jj++) {
            int j = jj * 128 + t;
            int k = j >> 6;
            int c = j & 63;
            float cv = css[c];
            float v  = g_xt[(bN + nbss[k]) * C + c];
            fTs[c * FT_STRIDE + k]        = v - cv;
            fTs[(64 + c) * FT_STRIDE + k] = cv;
        }
        asm volatile("bar.sync %0, 128;" :: "r"(barid));

        float acc[KNN];
#pragma unroll
        for (int k = 0; k < KNN; k++) acc[k] = 0.f;
#pragma unroll 4
        for (int c = 0; c < C2; c++) {
            float w = g_W1T[c * C2 + t];
            const float4* fr = (const float4*)(fTs + c * FT_STRIDE);
#pragma unroll
            for (int k4 = 0; k4 < 5; k4++) {
                float4 f = fr[k4];
                acc[4*k4+0] = fmaf(f.x, w, acc[4*k4+0]);
                acc[4*k4+1] = fmaf(f.y, w, acc[4*k4+1]);
                acc[4*k4+2] = fmaf(f.z, w, acc[4*k4+2]);
                acc[4*k4+3] = fmaf(f.w, w, acc[4*k4+3]);
            }
        }
        float mx = acc[0];
#pragma unroll
        for (int k = 1; k < KNN; k++) mx = fmaxf(mx, acc[k]);
        float ssum = 0.f;
#pragma unroll
        for (int k = 0; k < KNN; k++) { acc[k] = __expf(acc[k] - mx); ssum += acc[k]; }
        float inv = 1.f / ssum;

        float gacc = 0.f;
        {
            const float4* fr = (const float4*)(fTs + t * FT_STRIDE);
#pragma unroll
            for (int k4 = 0; k4 < 5; k4++) {
                float4 f = fr[k4];
                gacc = fmaf(f.x, acc[4*k4+0], gacc);
                gacc = fmaf(f.y, acc[4*k4+1], gacc);
                gacc = fmaf(f.z, acc[4*k4+2], gacc);
                gacc = fmaf(f.w, acc[4*k4+3], gacc);
            }
        }
        gss[t] = gacc * inv;
        asm volatile("bar.sync %0, 128;" :: "r"(barid));

        float oacc = 0.f;
#pragma unroll 8
        for (int c = 0; c < C2; c++)
            oacc = fmaf(gss[c], g_W2T[c * C2 + t], oacc);
        obuf[t * 33 + 2 * it + sub] = oacc;
        asm volatile("bar.sync %0, 128;" :: "r"(barid));
    }

    __syncthreads();
#pragma unroll
    for (int ii = 0; ii < (O * NB) / 256; ii++) {
        int i = ii * 256 + tid;
        int o = i >> 5, j = i & 31;
        out[((size_t)b * O + o) * N + n0 + j] = obuf[o * 33 + j];
    }
}

extern "C" void kernel_launch(void* const* d_in, const int* in_sizes, int n_in,
                              void* d_out, int out_size) {
    (void)in_sizes; (void)n_in; (void)out_size;
    const float* x  = (const float*)d_in[0];
    const float* W1 = (const float*)d_in[1];
    const float* W2 = (const float*)d_in[2];
    float* out = (float*)d_out;

    prep_kernel<<<(BATCH * N) / 256, 256>>>(x);
    wtrans_kernel<<<(C2 * C2) / 256, 256>>>(W1, W2);
    cudaFuncSetAttribute(knn_kernel, cudaFuncAttributeMaxDynamicSharedMemorySize,
                         KNN_SMEM_BYTES);
    knn_kernel<<<dim3(N / QT, BATCH), 128, KNN_SMEM_BYTES>>>();
    mlp_kernel<<<dim3(N / NB, BATCH), 256>>>(out);
}

// round 9
// speedup vs baseline: 2.2593x; 2.2593x over previous
#include <cuda_runtime.h>

#define BATCH 4
#define C 64
#define N 8192
#define O 128
#define KNN 20
#define C2 128
#define NB 32
#define FT_STRIDE 24

// kNN tiling
#define QT 64              // queries per block
#define CT 64              // candidates per tile
#define QS4 17             // query/cand tile row stride in float4 (68 floats)
#define DS_STRIDE 65       // distance tile row stride in floats

// Scratch (allocation-free rule: __device__ globals)
__device__ float g_xt[BATCH * N * C];    // (b, n, c) transposed points
__device__ float g_xx[BATCH * N];        // squared norms
__device__ int   g_idx[BATCH * N * KNN]; // knn indices
__device__ float g_W1T[C2 * C2];         // [c][d] = W1[d][c]
__device__ float g_W2T[C2 * C2];         // [c][o] = W2[o][c]

// ---------------------------------------------------------------------------
// Kernel 1: transpose x (b,c,n) -> xt (b,n,c) and compute squared norms
// ---------------------------------------------------------------------------
__global__ __launch_bounds__(256) void prep_kernel(const float* __restrict__ x) {
    int gid = blockIdx.x * 256 + threadIdx.x;     // gid = b*N + n
    int b = gid >> 13;
    int n = gid & (N - 1);
    const float* xb = x + (size_t)b * C * N;
    float v[C];
    float s = 0.f;
#pragma unroll
    for (int c = 0; c < C; c++) {
        v[c] = xb[(size_t)c * N + n];             // coalesced across threads
        s = fmaf(v[c], v[c], s);
    }
    g_xx[gid] = s;
    float4* dst = (float4*)(g_xt + (size_t)gid * C);
#pragma unroll
    for (int i = 0; i < C / 4; i++)
        dst[i] = make_float4(v[4*i], v[4*i+1], v[4*i+2], v[4*i+3]);
}

// ---------------------------------------------------------------------------
// Kernel 1b: transpose W1, W2 into global scratch (tiny)
// ---------------------------------------------------------------------------
__global__ __launch_bounds__(256) void wtrans_kernel(const float* __restrict__ W1,
                                                     const float* __restrict__ W2) {
    int i = blockIdx.x * 256 + threadIdx.x;       // i = d*128 + c
    int d = i >> 7, c = i & 127;
    g_W1T[c * C2 + d] = W1[i];
    g_W2T[c * C2 + d] = W2[i];
}

// ---------------------------------------------------------------------------
// Top-k insert: distances in registers (predicated unrolled update), index
// list in shared memory (column-major [slot*128 + t], conflict-free, written
// only on the rare hit path). Keeps register pressure low -> no spills.
// Only the SET of the 20 nearest matters (softmax over k is permutation-
// invariant), so no sorting anywhere.
// ---------------------------------------------------------------------------
__device__ __forceinline__ void topk_insert(float d, int m, float* bd,
                                            int* bi_col, int t,
                                            float& worst, int& wpos) {
    if (d < worst) {
#pragma unroll
        for (int i = 0; i < KNN; i++)
            if (i == wpos) bd[i] = d;
        bi_col[wpos * 128 + t] = m;
        worst = bd[0]; wpos = 0;
#pragma unroll
        for (int i = 1; i < KNN; i++)
            if (bd[i] > worst) { worst = bd[i]; wpos = i; }
    }
}

// ---------------------------------------------------------------------------
// Kernel 2: brute-force kNN, GEMM-style register-tiled distances.
// Block = 128 threads, 64 queries, 64-candidate tiles:
//   phase A: 4x8 per-thread register tile of dot products
//            (12 LDS.128 -> 128 FFMA per c4 chunk)
//   phase B: distances via smem; 2 threads per query scan disjoint halves.
// 61KB smem -> 3 blocks/SM (12 warps). ~95 regs/thread, no spills.
// ---------------------------------------------------------------------------
__global__ __launch_bounds__(128, 3) void knn_kernel() {
    extern __shared__ float sm[];
    float* qs  = sm;                       // [QT][68] query tile
    float* xs  = qs + QT * 68;             // [CT][68] candidate tile
    float* ds  = xs + CT * 68;             // [QT][DS_STRIDE] distances
    float* xxs = ds + QT * DS_STRIDE;      // [CT]
    int*   bic = (int*)(xxs + CT);         // [KNN][128] index lists (col-major)

    int t  = threadIdx.x;
    int tx = t & 7;                        // candidate lane: m = tx + 8*cj
    int ty = t >> 3;                       // query lane: q = ty + 16*qi
    int b  = blockIdx.y;
    size_t bN = (size_t)b * N;
    int q0 = blockIdx.x * QT;

    // Stage query tile (coalesced, stride-17 float4): 1024 float4 = 8 iters
    {
        const float4* src = (const float4*)(g_xt + (bN + q0) * C);
        float4* dst = (float4*)qs;
#pragma unroll
        for (int i = 0; i < 8; i++) {
            int j = i * 128 + t;
            dst[(j >> 4) * QS4 + (j & 15)] = src[j];
        }
    }

    float bd[KNN];
#pragma unroll
    for (int i = 0; i < KNN; i++) bd[i] = 3.4e38f;
    float worst = 3.4e38f;
    int   wpos  = 0;

    const float4* qb = (const float4*)qs + ty * QS4;   // query row base
    const float4* xb = (const float4*)xs + tx * QS4;   // candidate row base

    for (int m0 = 0; m0 < N; m0 += CT) {
        __syncthreads();
        // Candidate tile load (coalesced): 64 rows * 16 f4 = 1024 -> 8 iters
        {
            const float4* src = (const float4*)(g_xt + (bN + m0) * C);
            float4* dst = (float4*)xs;
#pragma unroll
            for (int i = 0; i < 8; i++) {
                int j = i * 128 + t;
                dst[(j >> 4) * QS4 + (j & 15)] = src[j];
            }
            if (t < CT) xxs[t] = g_xx[bN + m0 + t];
        }
        __syncthreads();

        // ---- phase A: 4x8 register tile of dot products ----
        float acc[4][8];
#pragma unroll
        for (int qi = 0; qi < 4; qi++)
#pragma unroll
            for (int cj = 0; cj < 8; cj++) acc[qi][cj] = 0.f;

#pragma unroll 4
        for (int i = 0; i < 16; i++) {
            float4 qf0 = qb[ 0 * QS4 + i];
            float4 qf1 = qb[16 * QS4 + i];
            float4 qf2 = qb[32 * QS4 + i];
            float4 qf3 = qb[48 * QS4 + i];
#pragma unroll
            for (int cj = 0; cj < 8; cj++) {
                float4 cf = xb[(8 * cj) * QS4 + i];
                acc[0][cj] = fmaf(qf0.x, cf.x, acc[0][cj]);
                acc[0][cj] = fmaf(qf0.y, cf.y, acc[0][cj]);
                acc[0][cj] = fmaf(qf0.z, cf.z, acc[0][cj]);
                acc[0][cj] = fmaf(qf0.w, cf.w, acc[0][cj]);
                acc[1][cj] = fmaf(qf1.x, cf.x, acc[1][cj]);
                acc[1][cj] = fmaf(qf1.y, cf.y, acc[1][cj]);
                acc[1][cj] = fmaf(qf1.z, cf.z, acc[1][cj]);
                acc[1][cj] = fmaf(qf1.w, cf.w, acc[1][cj]);
                acc[2][cj] = fmaf(qf2.x, cf.x, acc[2][cj]);
                acc[2][cj] = fmaf(qf2.y, cf.y, acc[2][cj]);
                acc[2][cj] = fmaf(qf2.z, cf.z, acc[2][cj]);
                acc[2][cj] = fmaf(qf2.w, cf.w, acc[2][cj]);
                acc[3][cj] = fmaf(qf3.x, cf.x, acc[3][cj]);
                acc[3][cj] = fmaf(qf3.y, cf.y, acc[3][cj]);
                acc[3][cj] = fmaf(qf3.z, cf.z, acc[3][cj]);
                acc[3][cj] = fmaf(qf3.w, cf.w, acc[3][cj]);
            }
        }

        // epilogue: d = xx_cand - 2*dot (xx_query constant per query ->
        // irrelevant for top-k ordering)
#pragma unroll
        for (int cj = 0; cj < 8; cj++) {
            float xc = xxs[tx + 8 * cj];
#pragma unroll
            for (int qi = 0; qi < 4; qi++)
                ds[(ty + 16 * qi) * DS_STRIDE + tx + 8 * cj] =
                    fmaf(-2.f, acc[qi][cj], xc);
        }
        __syncthreads();

        // ---- phase B: streaming top-k scan (2 threads per query) ----
        {
            int ql   = t & 63;
            int half = t >> 6;
            const float* dr = ds + ql * DS_STRIDE + half * 32;
            int mb = m0 + half * 32;
#pragma unroll 4
            for (int j = 0; j < 32; j++)
                topk_insert(dr[j], mb + j, bd, bic, t, worst, wpos);
        }
    }

    // Merge the two half-lists per query. Dump bd to smem (reuse qs).
    __syncthreads();
    float* md = qs;                          // [KNN][128] col-major dists
#pragma unroll
    for (int i = 0; i < KNN; i++) md[i * 128 + t] = bd[i];
    __syncthreads();
    if (t < 64) {
#pragma unroll
        for (int i = 0; i < KNN; i++) {
            float d = md[i * 128 + t + 64];
            int   m = bic[i * 128 + t + 64];
            topk_insert(d, m, bd, bic, t, worst, wpos);
        }
        int* op = g_idx + (bN + q0 + t) * KNN;
#pragma unroll
        for (int i = 0; i < KNN; i++) op[i] = bic[i * 128 + t];
    }
}

static const int KNN_SMEM_BYTES =
    (QT * 68 + CT * 68 + QT * DS_STRIDE + CT + KNN * 128) * 4;

// ---------------------------------------------------------------------------
// Kernel 3: gather feats, h = feats@W1^T, softmax over k, g[c]=sum_k f*gate,
// out[o] = sum_c g[c]*W2T[c][o].  (unchanged — known good)
// ---------------------------------------------------------------------------
__global__ __launch_bounds__(256) void mlp_kernel(float* __restrict__ out) {
    __shared__ float fT[2 * C2 * FT_STRIDE];
    __shared__ float cs[2 * C];
    __shared__ float gs[2 * C2];
    __shared__ int   nbs[2 * 32];
    __shared__ float obuf[O * 33];

    int tid = threadIdx.x;
    int sub = tid >> 7;
    int t   = tid & 127;
    int b   = blockIdx.y;
    int n0  = blockIdx.x * NB;
    int barid = sub + 1;

    float* fTs  = fT  + sub * C2 * FT_STRIDE;
    float* css  = cs  + sub * C;
    float* gss  = gs  + sub * C2;
    int*   nbss = nbs + sub * 32;
    size_t bN = (size_t)b * N;

    for (int it = 0; it < NB / 2; it++) {
        int n = n0 + 2 * it + sub;
        size_t base = bN + n;

        if (t < KNN) nbss[t] = g_idx[base * KNN + t];
        if (t < C)   css[t]  = g_xt[base * C + t];
        asm volatile("bar.sync %0, 128;" :: "r"(barid));

#pragma unroll
        for (int jj = 0; jj < (KNN * C) / 128; jj++) {
            int j = jj * 128 + t;
            int k = j >> 6;
            int c = j & 63;
            float cv = css[c];
            float v  = g_xt[(bN + nbss[k]) * C + c];
            fTs[c * FT_STRIDE + k]        = v - cv;
            fTs[(64 + c) * FT_STRIDE + k] = cv;
        }
        asm volatile("bar.sync %0, 128;" :: "r"(barid));

        float acc[KNN];
#pragma unroll
        for (int k = 0; k < KNN; k++) acc[k] = 0.f;
#pragma unroll 4
        for (int c = 0; c < C2; c++) {
            float w = g_W1T[c * C2 + t];
            const float4* fr = (const float4*)(fTs + c * FT_STRIDE);
#pragma unroll
            for (int k4 = 0; k4 < 5; k4++) {
                float4 f = fr[k4];
                acc[4*k4+0] = fmaf(f.x, w, acc[4*k4+0]);
                acc[4*k4+1] = fmaf(f.y, w, acc[4*k4+1]);
                acc[4*k4+2] = fmaf(f.z, w, acc[4*k4+2]);
                acc[4*k4+3] = fmaf(f.w, w, acc[4*k4+3]);
            }
        }
        float mx = acc[0];
#pragma unroll
        for (int k = 1; k < KNN; k++) mx = fmaxf(mx, acc[k]);
        float ssum = 0.f;
#pragma unroll
        for (int k = 0; k < KNN; k++) { acc[k] = __expf(acc[k] - mx); ssum += acc[k]; }
        float inv = 1.f / ssum;

        float gacc = 0.f;
        {
            const float4* fr = (const float4*)(fTs + t * FT_STRIDE);
#pragma unroll
            for (int k4 = 0; k4 < 5; k4++) {
                float4 f = fr[k4];
                gacc = fmaf(f.x, acc[4*k4+0], gacc);
                gacc = fmaf(f.y, acc[4*k4+1], gacc);
                gacc = fmaf(f.z, acc[4*k4+2], gacc);
                gacc = fmaf(f.w, acc[4*k4+3], gacc);
            }
        }
        gss[t] = gacc * inv;
        asm volatile("bar.sync %0, 128;" :: "r"(barid));

        float oacc = 0.f;
#pragma unroll 8
        for (int c = 0; c < C2; c++)
            oacc = fmaf(gss[c], g_W2T[c * C2 + t], oacc);
        obuf[t * 33 + 2 * it + sub] = oacc;
        asm volatile("bar.sync %0, 128;" :: "r"(barid));
    }

    __syncthreads();
#pragma unroll
    for (int ii = 0; ii < (O * NB) / 256; ii++) {
        int i = ii * 256 + tid;
        int o = i >> 5, j = i & 31;
        out[((size_t)b * O + o) * N + n0 + j] = obuf[o * 33 + j];
    }
}

extern "C" void kernel_launch(void* const* d_in, const int* in_sizes, int n_in,
                              void* d_out, int out_size) {
    (void)in_sizes; (void)n_in; (void)out_size;
    const float* x  = (const float*)d_in[0];
    const float* W1 = (const float*)d_in[1];
    const float* W2 = (const float*)d_in[2];
    float* out = (float*)d_out;

    prep_kernel<<<(BATCH * N) / 256, 256>>>(x);
    wtrans_kernel<<<(C2 * C2) / 256, 256>>>(W1, W2);
    cudaFuncSetAttribute(knn_kernel, cudaFuncAttributeMaxDynamicSharedMemorySize,
                         KNN_SMEM_BYTES);
    knn_kernel<<<dim3(N / QT, BATCH), 128, KNN_SMEM_BYTES>>>();
    mlp_kernel<<<dim3(N / NB, BATCH), 256>>>(out);
}

// round 10
// speedup vs baseline: 2.3909x; 1.0582x over previous
#include <cuda_runtime.h>

typedef unsigned long long u64;

#define BATCH 4
#define C 64
#define N 8192
#define O 128
#define KNN 20
#define C2 128
#define NB 32
#define FT_STRIDE 24

// kNN tiling
#define QT 64              // queries per block
#define CT 64              // candidates per tile
#define QS4 17             // row stride in 16B units (68 floats)
#define DS_STRIDE 65       // distance tile row stride in floats

// Scratch (allocation-free rule: __device__ globals)
__device__ float g_xt[BATCH * N * C];    // (b, n, c) transposed points
__device__ float g_xx[BATCH * N];        // squared norms
__device__ int   g_idx[BATCH * N * KNN]; // knn indices
__device__ float g_W1T[C2 * C2];         // [c][d] = W1[d][c]
__device__ float g_W2T[C2 * C2];         // [c][o] = W2[o][c]

// ---- packed fp32x2 helpers (sm_103a) --------------------------------------
__device__ __forceinline__ void fma2(u64& d, u64 a, u64 b) {
    asm("fma.rn.f32x2 %0, %1, %2, %0;" : "+l"(d) : "l"(a), "l"(b));
}
__device__ __forceinline__ u64 pk2(float v) {          // (v, v)
    u64 r; unsigned u = __float_as_uint(v);
    asm("mov.b64 %0, {%1, %1};" : "=l"(r) : "r"(u));
    return r;
}
__device__ __forceinline__ u64 pk2b(float lo, float hi) {
    u64 r;
    asm("mov.b64 %0, {%1, %2};" : "=l"(r) : "r"(__float_as_uint(lo)),
                                   "r"(__float_as_uint(hi)));
    return r;
}
__device__ __forceinline__ float psum(u64 a) {         // lo + hi
    return __uint_as_float((unsigned)a) + __uint_as_float((unsigned)(a >> 32));
}

// ---------------------------------------------------------------------------
// Kernel 1: transpose x (b,c,n) -> xt (b,n,c) and compute squared norms
// ---------------------------------------------------------------------------
__global__ __launch_bounds__(256) void prep_kernel(const float* __restrict__ x) {
    int gid = blockIdx.x * 256 + threadIdx.x;     // gid = b*N + n
    int b = gid >> 13;
    int n = gid & (N - 1);
    const float* xb = x + (size_t)b * C * N;
    float v[C];
    float s = 0.f;
#pragma unroll
    for (int c = 0; c < C; c++) {
        v[c] = xb[(size_t)c * N + n];             // coalesced across threads
        s = fmaf(v[c], v[c], s);
    }
    g_xx[gid] = s;
    float4* dst = (float4*)(g_xt + (size_t)gid * C);
#pragma unroll
    for (int i = 0; i < C / 4; i++)
        dst[i] = make_float4(v[4*i], v[4*i+1], v[4*i+2], v[4*i+3]);
}

// ---------------------------------------------------------------------------
// Kernel 1b: transpose W1, W2 into global scratch (tiny)
// ---------------------------------------------------------------------------
__global__ __launch_bounds__(256) void wtrans_kernel(const float* __restrict__ W1,
                                                     const float* __restrict__ W2) {
    int i = blockIdx.x * 256 + threadIdx.x;       // i = d*128 + c
    int d = i >> 7, c = i & 127;
    g_W1T[c * C2 + d] = W1[i];
    g_W2T[c * C2 + d] = W2[i];
}

// ---------------------------------------------------------------------------
// Top-k insert: distances in registers, index list in smem (column-major,
// conflict-free, written only on hit). Only the SET of the 20 nearest
// matters (softmax over k is permutation-invariant) -> no sorting.
// ---------------------------------------------------------------------------
__device__ __forceinline__ void topk_insert(float d, int m, float* bd,
                                            int* bi_col, int t,
                                            float& worst, int& wpos) {
    if (d < worst) {
#pragma unroll
        for (int i = 0; i < KNN; i++)
            if (i == wpos) bd[i] = d;
        bi_col[wpos * 128 + t] = m;
        worst = bd[0]; wpos = 0;
#pragma unroll
        for (int i = 1; i < KNN; i++)
            if (bd[i] > worst) { worst = bd[i]; wpos = i; }
    }
}

// ---------------------------------------------------------------------------
// Kernel 2: brute-force kNN, register-tiled distances with packed f32x2 FMA.
// Block = 128 threads, 64 queries, 64-candidate tiles:
//   phase A: 4x8 per-thread tile, FFMA2 over consecutive-c pairs
//            (1024 FFMA2 per thread per tile, no packing needed)
//   phase B: distances via smem; 2 threads per query scan disjoint halves.
// ---------------------------------------------------------------------------
__global__ __launch_bounds__(128, 3) void knn_kernel() {
    extern __shared__ float sm[];
    float* qs  = sm;                       // [QT][68] query tile
    float* xs  = qs + QT * 68;             // [CT][68] candidate tile
    float* ds  = xs + CT * 68;             // [QT][DS_STRIDE] distances
    float* xxs = ds + QT * DS_STRIDE;      // [CT]
    int*   bic = (int*)(xxs + CT);         // [KNN][128] index lists (col-major)

    int t  = threadIdx.x;
    int tx = t & 7;                        // candidate lane: m = tx + 8*cj
    int ty = t >> 3;                       // query lane: q = ty + 16*qi
    int b  = blockIdx.y;
    size_t bN = (size_t)b * N;
    int q0 = blockIdx.x * QT;

    // Stage query tile (coalesced, stride-17 float4): 1024 float4 = 8 iters
    {
        const float4* src = (const float4*)(g_xt + (bN + q0) * C);
        float4* dst = (float4*)qs;
#pragma unroll
        for (int i = 0; i < 8; i++) {
            int j = i * 128 + t;
            dst[(j >> 4) * QS4 + (j & 15)] = src[j];
        }
    }

    float bd[KNN];
#pragma unroll
    for (int i = 0; i < KNN; i++) bd[i] = 3.4e38f;
    float worst = 3.4e38f;
    int   wpos  = 0;

    const ulonglong2* qb = (const ulonglong2*)qs + ty * QS4;  // 16B units
    const ulonglong2* xb = (const ulonglong2*)xs + tx * QS4;

    for (int m0 = 0; m0 < N; m0 += CT) {
        __syncthreads();
        // Candidate tile load (coalesced): 64 rows * 16 f4 = 1024 -> 8 iters
        {
            const float4* src = (const float4*)(g_xt + (bN + m0) * C);
            float4* dst = (float4*)xs;
#pragma unroll
            for (int i = 0; i < 8; i++) {
                int j = i * 128 + t;
                dst[(j >> 4) * QS4 + (j & 15)] = src[j];
            }
            if (t < CT) xxs[t] = g_xx[bN + m0 + t];
        }
        __syncthreads();

        // ---- phase A: 4x8 tile of dot products, f32x2 packed over c ----
        u64 acc2[4][8];
#pragma unroll
        for (int qi = 0; qi < 4; qi++)
#pragma unroll
            for (int cj = 0; cj < 8; cj++) acc2[qi][cj] = 0ull;

#pragma unroll 4
        for (int i = 0; i < 16; i++) {
            ulonglong2 q0p = qb[ 0 * QS4 + i];
            ulonglong2 q1p = qb[16 * QS4 + i];
            ulonglong2 q2p = qb[32 * QS4 + i];
            ulonglong2 q3p = qb[48 * QS4 + i];
#pragma unroll
            for (int cj = 0; cj < 8; cj++) {
                ulonglong2 cf = xb[(8 * cj) * QS4 + i];
                fma2(acc2[0][cj], q0p.x, cf.x);
                fma2(acc2[0][cj], q0p.y, cf.y);
                fma2(acc2[1][cj], q1p.x, cf.x);
                fma2(acc2[1][cj], q1p.y, cf.y);
                fma2(acc2[2][cj], q2p.x, cf.x);
                fma2(acc2[2][cj], q2p.y, cf.y);
                fma2(acc2[3][cj], q3p.x, cf.x);
                fma2(acc2[3][cj], q3p.y, cf.y);
            }
        }

        // epilogue: d = xx_cand - 2*dot (xx_query constant per query ->
        // irrelevant for top-k ordering)
#pragma unroll
        for (int cj = 0; cj < 8; cj++) {
            float xc = xxs[tx + 8 * cj];
#pragma unroll
            for (int qi = 0; qi < 4; qi++)
                ds[(ty + 16 * qi) * DS_STRIDE + tx + 8 * cj] =
                    fmaf(-2.f, psum(acc2[qi][cj]), xc);
        }
        __syncthreads();

        // ---- phase B: streaming top-k scan (2 threads per query) ----
        {
            int ql   = t & 63;
            int half = t >> 6;
            const float* dr = ds + ql * DS_STRIDE + half * 32;
            int mb = m0 + half * 32;
#pragma unroll 4
            for (int j = 0; j < 32; j++)
                topk_insert(dr[j], mb + j, bd, bic, t, worst, wpos);
        }
    }

    // Merge the two half-lists per query. Dump bd to smem (reuse qs).
    __syncthreads();
    float* md = qs;                          // [KNN][128] col-major dists
#pragma unroll
    for (int i = 0; i < KNN; i++) md[i * 128 + t] = bd[i];
    __syncthreads();
    if (t < 64) {
#pragma unroll
        for (int i = 0; i < KNN; i++) {
            float d = md[i * 128 + t + 64];
            int   m = bic[i * 128 + t + 64];
            topk_insert(d, m, bd, bic, t, worst, wpos);
        }
        int* op = g_idx + (bN + q0 + t) * KNN;
#pragma unroll
        for (int i = 0; i < KNN; i++) op[i] = bic[i * 128 + t];
    }
}

static const int KNN_SMEM_BYTES =
    (QT * 68 + CT * 68 + QT * DS_STRIDE + CT + KNN * 128) * 4;

// ---------------------------------------------------------------------------
// Kernel 3: gather feats, h = feats@W1^T, softmax over k, g[c]=sum_k f*gate,
// out[o] = sum_c g[c]*W2T[c][o].  Hot loops converted to f32x2 over k-pairs.
// ---------------------------------------------------------------------------
__global__ __launch_bounds__(256) void mlp_kernel(float* __restrict__ out) {
    __shared__ float fT[2 * C2 * FT_STRIDE];
    __shared__ float cs[2 * C];
    __shared__ float gs[2 * C2];
    __shared__ int   nbs[2 * 32];
    __shared__ float obuf[O * 33];

    int tid = threadIdx.x;
    int sub = tid >> 7;
    int t   = tid & 127;
    int b   = blockIdx.y;
    int n0  = blockIdx.x * NB;
    int barid = sub + 1;

    float* fTs  = fT  + sub * C2 * FT_STRIDE;
    float* css  = cs  + sub * C;
    float* gss  = gs  + sub * C2;
    int*   nbss = nbs + sub * 32;
    size_t bN = (size_t)b * N;

    for (int it = 0; it < NB / 2; it++) {
        int n = n0 + 2 * it + sub;
        size_t base = bN + n;

        if (t < KNN) nbss[t] = g_idx[base * KNN + t];
        if (t < C)   css[t]  = g_xt[base * C + t];
        asm volatile("bar.sync %0, 128;" :: "r"(barid));

#pragma unroll
        for (int jj = 0; jj < (KNN * C) / 128; jj++) {
            int j = jj * 128 + t;
            int k = j >> 6;
            int c = j & 63;
            float cv = css[c];
            float v  = g_xt[(bN + nbss[k]) * C + c];
            fTs[c * FT_STRIDE + k]        = v - cv;
            fTs[(64 + c) * FT_STRIDE + k] = cv;
        }
        asm volatile("bar.sync %0, 128;" :: "r"(barid));

        // phase 2: h[k] for d=t via f32x2 over k-pairs (10 FFMA2 per c)
        u64 acc2[KNN / 2];
#pragma unroll
        for (int k = 0; k < KNN / 2; k++) acc2[k] = 0ull;
#pragma unroll 4
        for (int c = 0; c < C2; c++) {
            u64 w2 = pk2(g_W1T[c * C2 + t]);       // (w, w)
            const ulonglong2* fr = (const ulonglong2*)(fTs + c * FT_STRIDE);
#pragma unroll
            for (int k4 = 0; k4 < 5; k4++) {
                ulonglong2 f = fr[k4];             // 4 consecutive k's
                fma2(acc2[2*k4+0], f.x, w2);
                fma2(acc2[2*k4+1], f.y, w2);
            }
        }
        float acc[KNN];
#pragma unroll
        for (int k = 0; k < KNN / 2; k++) {
            acc[2*k]   = __uint_as_float((unsigned)acc2[k]);
            acc[2*k+1] = __uint_as_float((unsigned)(acc2[k] >> 32));
        }
        float mx = acc[0];
#pragma unroll
        for (int k = 1; k < KNN; k++) mx = fmaxf(mx, acc[k]);
        float ssum = 0.f;
#pragma unroll
        for (int k = 0; k < KNN; k++) { acc[k] = __expf(acc[k] - mx); ssum += acc[k]; }
        float inv = 1.f / ssum;

        // gated sum for c=t via f32x2
        u64 g2 = 0ull;
        {
            const ulonglong2* fr = (const ulonglong2*)(fTs + t * FT_STRIDE);
#pragma unroll
            for (int k4 = 0; k4 < 5; k4++) {
                ulonglong2 f = fr[k4];
                fma2(g2, f.x, pk2b(acc[4*k4+0], acc[4*k4+1]));
                fma2(g2, f.y, pk2b(acc[4*k4+2], acc[4*k4+3]));
            }
        }
        gss[t] = psum(g2) * inv;
        asm volatile("bar.sync %0, 128;" :: "r"(barid));

        float oacc = 0.f;
#pragma unroll 8
        for (int c = 0; c < C2; c++)
            oacc = fmaf(gss[c], g_W2T[c * C2 + t], oacc);
        obuf[t * 33 + 2 * it + sub] = oacc;
        asm volatile("bar.sync %0, 128;" :: "r"(barid));
    }

    __syncthreads();
#pragma unroll
    for (int ii = 0; ii < (O * NB) / 256; ii++) {
        int i = ii * 256 + tid;
        int o = i >> 5, j = i & 31;
        out[((size_t)b * O + o) * N + n0 + j] = obuf[o * 33 + j];
    }
}

extern "C" void kernel_launch(void* const* d_in, const int* in_sizes, int n_in,
                              void* d_out, int out_size) {
    (void)in_sizes; (void)n_in; (void)out_size;
    const float* x  = (const float*)d_in[0];
    const float* W1 = (const float*)d_in[1];
    const float* W2 = (const float*)d_in[2];
    float* out = (float*)d_out;

    prep_kernel<<<(BATCH * N) / 256, 256>>>(x);
    wtrans_kernel<<<(C2 * C2) / 256, 256>>>(W1, W2);
    cudaFuncSetAttribute(knn_kernel, cudaFuncAttributeMaxDynamicSharedMemorySize,
                         KNN_SMEM_BYTES);
    knn_kernel<<<dim3(N / QT, BATCH), 128, KNN_SMEM_BYTES>>>();
    mlp_kernel<<<dim3(N / NB, BATCH), 256>>>(out);
}

// round 14
// speedup vs baseline: 2.8432x; 1.1892x over previous
#include <cuda_runtime.h>
#include <cuda_bf16.h>

typedef unsigned long long u64;
typedef unsigned int u32;

#define BATCH 4
#define C 64
#define N 8192
#define O 128
#define KNN 20
#define C2 128
#define NB 32
#define FT_STRIDE 24

// kNN HMMA tiling
#define QT 64              // queries per block (4 warps x m16)
#define NT 128             // candidates per tile (16 n-tiles of 8)
#define AS 36              // A/B smem row stride in u32 (conflict-free: 36g+c = 4g+c mod 32)
#define DSK 129            // distance tile row stride (floats)

// Scratch (allocation-free rule: __device__ globals)
__device__ float g_xt[BATCH * N * C];    // (b, n, c) fp32 points
__device__ float g_xx[BATCH * N];        // squared norms
__device__ u32   g_xhi[BATCH * N * 32];  // bf16x2 hi pairs (c-major, 32 u32/point)
__device__ u32   g_xlo[BATCH * N * 32];  // bf16x2 lo pairs
__device__ int   g_idx[BATCH * N * KNN]; // knn indices
__device__ float g_W1T[C2 * C2];         // [c][d] = W1[d][c]
__device__ float g_W2T[C2 * C2];         // [c][o] = W2[o][c]

// ---- packed fp32x2 helpers (MLP) ------------------------------------------
__device__ __forceinline__ void fma2(u64& d, u64 a, u64 b) {
    asm("fma.rn.f32x2 %0, %1, %2, %0;" : "+l"(d) : "l"(a), "l"(b));
}
__device__ __forceinline__ u64 pk2(float v) {
    u64 r; unsigned u = __float_as_uint(v);
    asm("mov.b64 %0, {%1, %1};" : "=l"(r) : "r"(u));
    return r;
}
__device__ __forceinline__ u64 pk2b(float lo, float hi) {
    u64 r;
    asm("mov.b64 %0, {%1, %2};" : "=l"(r) : "r"(__float_as_uint(lo)),
                                   "r"(__float_as_uint(hi)));
    return r;
}
__device__ __forceinline__ float psum(u64 a) {
    return __uint_as_float((unsigned)a) + __uint_as_float((unsigned)(a >> 32));
}

// ---- HMMA m16n8k16 bf16 (base-target instruction, sm_80+) -----------------
__device__ __forceinline__ void mma16816(float* d, u32 a0, u32 a1, u32 a2,
                                         u32 a3, u32 b0, u32 b1) {
    asm volatile(
        "mma.sync.aligned.m16n8k16.row.col.f32.bf16.bf16.f32 "
        "{%0,%1,%2,%3}, {%4,%5,%6,%7}, {%8,%9}, {%0,%1,%2,%3};"
        : "+f"(d[0]), "+f"(d[1]), "+f"(d[2]), "+f"(d[3])
        : "r"(a0), "r"(a1), "r"(a2), "r"(a3), "r"(b0), "r"(b1));
}

// ---------------------------------------------------------------------------
// Kernel 1: transpose + norms + bf16 hi/lo split
// ---------------------------------------------------------------------------
__global__ __launch_bounds__(256) void prep_kernel(const float* __restrict__ x) {
    int gid = blockIdx.x * 256 + threadIdx.x;     // gid = b*N + n
    int b = gid >> 13;
    int n = gid & (N - 1);
    const float* xb = x + (size_t)b * C * N;
    float v[C];
    float s = 0.f;
#pragma unroll
    for (int c = 0; c < C; c++) {
        v[c] = xb[(size_t)c * N + n];             // coalesced across threads
        s = fmaf(v[c], v[c], s);
    }
    g_xx[gid] = s;
    float4* dst = (float4*)(g_xt + (size_t)gid * C);
#pragma unroll
    for (int i = 0; i < C / 4; i++)
        dst[i] = make_float4(v[4*i], v[4*i+1], v[4*i+2], v[4*i+3]);
    u32* hp = g_xhi + (size_t)gid * 32;
    u32* lp = g_xlo + (size_t)gid * 32;
#pragma unroll
    for (int i = 0; i < 32; i++) {
        float v0 = v[2*i], v1 = v[2*i+1];
        __nv_bfloat16 h0 = __float2bfloat16(v0);
        __nv_bfloat16 h1 = __float2bfloat16(v1);
        __nv_bfloat16 l0 = __float2bfloat16(v0 - __bfloat162float(h0));
        __nv_bfloat16 l1 = __float2bfloat16(v1 - __bfloat162float(h1));
        hp[i] = (u32)__bfloat16_as_ushort(h0) | ((u32)__bfloat16_as_ushort(h1) << 16);
        lp[i] = (u32)__bfloat16_as_ushort(l0) | ((u32)__bfloat16_as_ushort(l1) << 16);
    }
}

// ---------------------------------------------------------------------------
// Kernel 1b: transpose W1, W2 into global scratch (tiny)
// ---------------------------------------------------------------------------
__global__ __launch_bounds__(256) void wtrans_kernel(const float* __restrict__ W1,
                                                     const float* __restrict__ W2) {
    int i = blockIdx.x * 256 + threadIdx.x;       // i = d*128 + c
    int d = i >> 7, c = i & 127;
    g_W1T[c * C2 + d] = W1[i];
    g_W2T[c * C2 + d] = W2[i];
}

// ---------------------------------------------------------------------------
// Top-k insert: distances in registers, index list in smem (column-major,
// conflict-free, written only on hit). Only the SET of the 20 nearest
// matters (softmax over k is permutation-invariant) -> no sorting.
// ---------------------------------------------------------------------------
__device__ __forceinline__ void topk_insert(float d, int m, float* bd,
                                            int* bi_col, int t,
                                            float& worst, int& wpos) {
    if (d < worst) {
#pragma unroll
        for (int i = 0; i < KNN; i++)
            if (i == wpos) bd[i] = d;
        bi_col[wpos * 128 + t] = m;
        worst = bd[0]; wpos = 0;
#pragma unroll
        for (int i = 1; i < KNN; i++)
            if (bd[i] > worst) { worst = bd[i]; wpos = i; }
    }
}

// ---------------------------------------------------------------------------
// Kernel 2: kNN via HMMA bf16-split 3-GEMM distances.
//   dot_fp32 ~= Ahi.Bhi^T + Ahi.Blo^T + Alo.Bhi^T  (residual ~3e-5)
// 128 threads = 4 warps; 64 queries/block (warp w -> rows 16w..16w+15);
// 128-candidate tiles, 16 n-tiles, 64 f32 accum regs/thread, 12 k16-steps.
// Fragment gathers: plain u32 LDS, conflict-free by row stride AS=36.
// Then d = xx - 2*dot -> 64x129 smem tile -> round-9 scan/merge machinery.
// ---------------------------------------------------------------------------
#define SM_A_HI 512
#define SM_A_LO (SM_A_HI + QT * AS * 4)            // +9216
#define SM_B_HI (SM_A_LO + QT * AS * 4)
#define SM_B_LO (SM_B_HI + NT * AS * 4)            // +18432
#define SM_DS   (SM_B_LO + NT * AS * 4)
#define SM_BIC  (SM_DS + QT * DSK * 4)             // +33024
#define KNN_SMEM_BYTES (SM_BIC + KNN * 128 * 4)

__global__ __launch_bounds__(128) void knn_kernel() {
    extern __shared__ char smem[];
    float* xxs = (float*)smem;                     // [NT]
    u32* Ahi = (u32*)(smem + SM_A_HI);
    u32* Alo = (u32*)(smem + SM_A_LO);
    u32* Bhi = (u32*)(smem + SM_B_HI);
    u32* Blo = (u32*)(smem + SM_B_LO);
    float* ds = (float*)(smem + SM_DS);            // [QT][DSK]
    int*   bic = (int*)(smem + SM_BIC);            // [KNN][128]

    int t    = threadIdx.x;
    int w    = t >> 5;
    int lane = t & 31;
    int g    = lane >> 2;                          // fragment group 0..7
    int tig  = lane & 3;                           // thread-in-group
    int b    = blockIdx.y;
    size_t bN = (size_t)b * N;
    int q0 = blockIdx.x * QT;
    int m0 = w * 16;                               // warp's query m-tile base

    // Stationary A tiles (hi/lo): 64 rows x 8 float4, smem stride 9 f4 (=36 u32)
    {
        const float4* sh = (const float4*)g_xhi + (bN + q0) * 8;
        const float4* sl = (const float4*)g_xlo + (bN + q0) * 8;
        float4* dh = (float4*)Ahi;
        float4* dl = (float4*)Alo;
#pragma unroll
        for (int i = 0; i < 4; i++) {
            int j = i * 128 + t;
            int r = j >> 3, c4 = j & 7;
            dh[r * 9 + c4] = sh[j];
            dl[r * 9 + c4] = sl[j];
        }
    }

    float bd[KNN];
#pragma unroll
    for (int i = 0; i < KNN; i++) bd[i] = 3.4e38f;
    float worst = 3.4e38f;
    int   wpos  = 0;

    for (int n0 = 0; n0 < N; n0 += NT) {
        __syncthreads();   // prev ds consumed / A staged
        // B tile load (128 rows x 8 f4) + candidate norms
        {
            const float4* sh = (const float4*)g_xhi + (bN + n0) * 8;
            const float4* sl = (const float4*)g_xlo + (bN + n0) * 8;
            float4* dh = (float4*)Bhi;
            float4* dl = (float4*)Blo;
#pragma unroll
            for (int i = 0; i < 8; i++) {
                int j = i * 128 + t;
                int r = j >> 3, c4 = j & 7;
                dh[r * 9 + c4] = sh[j];
                dl[r * 9 + c4] = sl[j];
            }
            xxs[t] = g_xx[bN + n0 + t];
        }
        __syncthreads();

        // ---- GEMM: 12 k16-steps accumulated into 16 n-tiles x 4 regs ----
        float acc[16][4];
#pragma unroll
        for (int nt = 0; nt < 16; nt++)
#pragma unroll
            for (int r = 0; r < 4; r++) acc[nt][r] = 0.f;

#pragma unroll
        for (int pass = 0; pass < 3; pass++) {
            const u32* Ab = (pass == 2) ? Alo : Ahi;
            const u32* Bb = (pass == 1) ? Blo : Bhi;
#pragma unroll
            for (int ks = 0; ks < 4; ks++) {
                int ab = (m0 + g) * AS + ks * 8 + tig;
                u32 a0 = Ab[ab];
                u32 a1 = Ab[ab + 8 * AS];
                u32 a2 = Ab[ab + 4];
                u32 a3 = Ab[ab + 8 * AS + 4];
#pragma unroll
                for (int nt = 0; nt < 16; nt++) {
                    int bb = (nt * 8 + g) * AS + ks * 8 + tig;
                    u32 b0 = Bb[bb];
                    u32 b1 = Bb[bb + 4];
                    mma16816(acc[nt], a0, a1, a2, a3, b0, b1);
                }
            }
        }

        // epilogue: d = xx_cand - 2*dot  (xx_query constant per row)
#pragma unroll
        for (int nt = 0; nt < 16; nt++) {
            int col = nt * 8 + 2 * tig;
            float x0 = xxs[col], x1 = xxs[col + 1];
            float* r0 = ds + (m0 + g) * DSK + col;
            float* r1 = ds + (m0 + g + 8) * DSK + col;
            r0[0] = fmaf(-2.f, acc[nt][0], x0);
            r0[1] = fmaf(-2.f, acc[nt][1], x1);
            r1[0] = fmaf(-2.f, acc[nt][2], x0);
            r1[1] = fmaf(-2.f, acc[nt][3], x1);
        }
        __syncthreads();

        // ---- scan: 2 threads per query over disjoint 64-col halves ----
        {
            int ql   = t & 63;
            int half = t >> 6;
            const float* dr = ds + ql * DSK + half * 64;
            int mb = n0 + half * 64;
#pragma unroll 4
            for (int j = 0; j < 64; j++)
                topk_insert(dr[j], mb + j, bd, bic, t, worst, wpos);
        }
    }

    // Merge the two half-lists per query (reuse ds for dists)
    __syncthreads();
    float* md = ds;                                 // [KNN][128] col-major
#pragma unroll
    for (int i = 0; i < KNN; i++) md[i * 128 + t] = bd[i];
    __syncthreads();
    if (t < 64) {
#pragma unroll
        for (int i = 0; i < KNN; i++) {
            float d = md[i * 128 + t + 64];
            int   m = bic[i * 128 + t + 64];
            topk_insert(d, m, bd, bic, t, worst, wpos);
        }
        int* op = g_idx + (bN + q0 + t) * KNN;
#pragma unroll
        for (int i = 0; i < KNN; i++) op[i] = bic[i * 128 + t];
    }
}

// ---------------------------------------------------------------------------
// Kernel 3: gather feats, h = feats@W1^T, softmax over k, g[c]=sum_k f*gate,
// out[o] = sum_c g[c]*W2T[c][o].  (unchanged from round 10 — known good)
// ---------------------------------------------------------------------------
__global__ __launch_bounds__(256) void mlp_kernel(float* __restrict__ out) {
    __shared__ float fT[2 * C2 * FT_STRIDE];
    __shared__ float cs[2 * C];
    __shared__ float gs[2 * C2];
    __shared__ int   nbs[2 * 32];
    __shared__ float obuf[O * 33];

    int tid = threadIdx.x;
    int sub = tid >> 7;
    int t   = tid & 127;
    int b   = blockIdx.y;
    int n0  = blockIdx.x * NB;
    int barid = sub + 1;

    float* fTs  = fT  + sub * C2 * FT_STRIDE;
    float* css  = cs  + sub * C;
    float* gss  = gs  + sub * C2;
    int*   nbss = nbs + sub * 32;
    size_t bN = (size_t)b * N;

    for (int it = 0; it < NB / 2; it++) {
        int n = n0 + 2 * it + sub;
        size_t base = bN + n;

        if (t < KNN) nbss[t] = g_idx[base * KNN + t];
        if (t < C)   css[t]  = g_xt[base * C + t];
        asm volatile("bar.sync %0, 128;" :: "r"(barid));

#pragma unroll
        for (int jj = 0; jj < (KNN * C) / 128; jj++) {
            int j = jj * 128 + t;
            int k = j >> 6;
            int c = j & 63;
            float cv = css[c];
            float v  = g_xt[(bN + nbss[k]) * C + c];
            fTs[c * FT_STRIDE + k]        = v - cv;
            fTs[(64 + c) * FT_STRIDE + k] = cv;
        }
        asm volatile("bar.sync %0, 128;" :: "r"(barid));

        u64 acc2[KNN / 2];
#pragma unroll
        for (int k = 0; k < KNN / 2; k++) acc2[k] = 0ull;
#pragma unroll 4
        for (int c = 0; c < C2; c++) {
            u64 w2 = pk2(g_W1T[c * C2 + t]);
            const ulonglong2* fr = (const ulonglong2*)(fTs + c * FT_STRIDE);
#pragma unroll
            for (int k4 = 0; k4 < 5; k4++) {
                ulonglong2 f = fr[k4];
                fma2(acc2[2*k4+0], f.x, w2);
                fma2(acc2[2*k4+1], f.y, w2);
            }
        }
        float acc[KNN];
#pragma unroll
        for (int k = 0; k < KNN / 2; k++) {
            acc[2*k]   = __uint_as_float((unsigned)acc2[k]);
            acc[2*k+1] = __uint_as_float((unsigned)(acc2[k] >> 32));
        }
        float mx = acc[0];
#pragma unroll
        for (int k = 1; k < KNN; k++) mx = fmaxf(mx, acc[k]);
        float ssum = 0.f;
#pragma unroll
        for (int k = 0; k < KNN; k++) { acc[k] = __expf(acc[k] - mx); ssum += acc[k]; }
        float inv = 1.f / ssum;

        u64 g2 = 0ull;
        {
            const ulonglong2* fr = (const ulonglong2*)(fTs + t * FT_STRIDE);
#pragma unroll
            for (int k4 = 0; k4 < 5; k4++) {
                ulonglong2 f = fr[k4];
                fma2(g2, f.x, pk2b(acc[4*k4+0], acc[4*k4+1]));
                fma2(g2, f.y, pk2b(acc[4*k4+2], acc[4*k4+3]));
            }
        }
        gss[t] = psum(g2) * inv;
        asm volatile("bar.sync %0, 128;" :: "r"(barid));

        float oacc = 0.f;
#pragma unroll 8
        for (int c = 0; c < C2; c++)
            oacc = fmaf(gss[c], g_W2T[c * C2 + t], oacc);
        obuf[t * 33 + 2 * it + sub] = oacc;
        asm volatile("bar.sync %0, 128;" :: "r"(barid));
    }

    __syncthreads();
#pragma unroll
    for (int ii = 0; ii < (O * NB) / 256; ii++) {
        int i = ii * 256 + tid;
        int o = i >> 5, j = i & 31;
        out[((size_t)b * O + o) * N + n0 + j] = obuf[o * 33 + j];
    }
}

extern "C" void kernel_launch(void* const* d_in, const int* in_sizes, int n_in,
                              void* d_out, int out_size) {
    (void)in_sizes; (void)n_in; (void)out_size;
    const float* x  = (const float*)d_in[0];
    const float* W1 = (const float*)d_in[1];
    const float* W2 = (const float*)d_in[2];
    float* out = (float*)d_out;

    prep_kernel<<<(BATCH * N) / 256, 256>>>(x);
    wtrans_kernel<<<(C2 * C2) / 256, 256>>>(W1, W2);
    cudaFuncSetAttribute(knn_kernel, cudaFuncAttributeMaxDynamicSharedMemorySize,
                         KNN_SMEM_BYTES);
    knn_kernel<<<dim3(N / QT, BATCH), 128, KNN_SMEM_BYTES>>>();
    mlp_kernel<<<dim3(N / NB, BATCH), 256>>>(out);
}